// round 2
// baseline (speedup 1.0000x reference)
#include <cuda_runtime.h>

// Problem constants (fixed by the reference)
#define T_DIM 1024
#define B_DIM 256
#define I_DIM 256
#define H_DIM 256
#define M_DIM (T_DIM * B_DIM)   // 262144 rows of the input-projection GEMM

// Scratch for X = inputs @ W_xh + b_h  (fp32, 268 MB) — __device__ global per harness rules.
__device__ float g_X[(size_t)M_DIM * H_DIM];

// ---------------------------------------------------------------------------
// Kernel 1: X = inputs @ W_xh + b_h     (M=262144, K=256, N=256, fp32 SGEMM)
// Classic 128x128x8 register-blocked tile, 256 threads, 8x8 per thread.
// ---------------------------------------------------------------------------
#define BM 128
#define BN 128
#define BK 8
#define TM 8
#define TN 8

__global__ __launch_bounds__(256) void gemm_xh_kernel(
    const float* __restrict__ A,     // [M_DIM, I_DIM]
    const float* __restrict__ Bw,    // [I_DIM, H_DIM]
    const float* __restrict__ bias)  // [H_DIM]
{
    __shared__ float As[BK * BM];   // transposed: As[k][m]
    __shared__ float Bs[BK * BN];   // Bs[k][n]

    const int mTile = blockIdx.x;
    const int nTile = blockIdx.y;
    const int tid = threadIdx.x;

    const int tx = tid % (BN / TN);   // 0..15
    const int ty = tid / (BN / TN);   // 0..15

    const int aRow = tid >> 1;          // 0..127
    const int aCol = (tid & 1) * 4;     // 0 or 4
    const int bRow = tid >> 5;          // 0..7
    const int bCol = (tid & 31) * 4;    // 0..124

    const float* Ag = A + (size_t)mTile * BM * I_DIM;
    const float* Bg = Bw + nTile * BN;

    float acc[TM][TN];
#pragma unroll
    for (int i = 0; i < TM; i++)
#pragma unroll
        for (int j = 0; j < TN; j++) acc[i][j] = 0.0f;

    for (int k0 = 0; k0 < I_DIM; k0 += BK) {
        // Load A tile (128x8) transposed into smem
        float4 a = *(const float4*)&Ag[(size_t)aRow * I_DIM + k0 + aCol];
        As[(aCol + 0) * BM + aRow] = a.x;
        As[(aCol + 1) * BM + aRow] = a.y;
        As[(aCol + 2) * BM + aRow] = a.z;
        As[(aCol + 3) * BM + aRow] = a.w;
        // Load B tile (8x128)
        float4 b = *(const float4*)&Bg[(size_t)(k0 + bRow) * H_DIM + bCol];
        *(float4*)&Bs[bRow * BN + bCol] = b;
        __syncthreads();

#pragma unroll
        for (int k = 0; k < BK; k++) {
            float rM[TM], rN[TN];
            float4 m0 = *(const float4*)&As[k * BM + ty * TM + 0];
            float4 m1 = *(const float4*)&As[k * BM + ty * TM + 4];
            rM[0] = m0.x; rM[1] = m0.y; rM[2] = m0.z; rM[3] = m0.w;
            rM[4] = m1.x; rM[5] = m1.y; rM[6] = m1.z; rM[7] = m1.w;
            float4 n0 = *(const float4*)&Bs[k * BN + tx * TN + 0];
            float4 n1 = *(const float4*)&Bs[k * BN + tx * TN + 4];
            rN[0] = n0.x; rN[1] = n0.y; rN[2] = n0.z; rN[3] = n0.w;
            rN[4] = n1.x; rN[5] = n1.y; rN[6] = n1.z; rN[7] = n1.w;
#pragma unroll
            for (int i = 0; i < TM; i++)
#pragma unroll
                for (int j = 0; j < TN; j++)
                    acc[i][j] = fmaf(rM[i], rN[j], acc[i][j]);
        }
        __syncthreads();
    }

    // Epilogue: add bias, store
    const int nBase = nTile * BN + tx * TN;
    float bv[TN];
#pragma unroll
    for (int j = 0; j < TN; j++) bv[j] = bias[nBase + j];

#pragma unroll
    for (int i = 0; i < TM; i++) {
        size_t row = (size_t)mTile * BM + ty * TM + i;
        float4 o0, o1;
        o0.x = acc[i][0] + bv[0]; o0.y = acc[i][1] + bv[1];
        o0.z = acc[i][2] + bv[2]; o0.w = acc[i][3] + bv[3];
        o1.x = acc[i][4] + bv[4]; o1.y = acc[i][5] + bv[5];
        o1.z = acc[i][6] + bv[6]; o1.w = acc[i][7] + bv[7];
        *(float4*)&g_X[row * H_DIM + nBase + 0] = o0;
        *(float4*)&g_X[row * H_DIM + nBase + 4] = o1;
    }
}

// ---------------------------------------------------------------------------
// Kernel 2: the recurrence.
// 128 CTAs x 256 threads. CTA c owns batch rows 2c, 2c+1 — rows are fully
// independent across CTAs, so no grid sync is ever needed.
// W_hh: first 224 k-rows live in smem (fp32), last 32 k-rows live permanently
// in registers (64 floats/thread). State (2x256 fp32) lives in smem.
// Thread t: row r = t>>7, output columns h0 = 2*(t&127), h0+1.
// ---------------------------------------------------------------------------
#define KS 224
#define RNN_SMEM_FLOATS (KS * H_DIM + 2 * H_DIM)
#define RNN_SMEM_BYTES (RNN_SMEM_FLOATS * 4)   // 231424 <= 232448

__global__ __launch_bounds__(256, 1) void rnn_kernel(
    const float* __restrict__ W_hh,   // [H_DIM, H_DIM] (k, h)
    float* __restrict__ out,          // outputs [T,B,H] then (optionally) state [B,H]
    int write_state)
{
    extern __shared__ float sm[];
    float* Wsh = sm;                  // [KS][H_DIM]
    float* S = sm + KS * H_DIM;       // [2][H_DIM]

    const int tid = threadIdx.x;
    const int r = tid >> 7;           // 0 or 1
    const int h0 = (tid & 127) * 2;
    const int b = blockIdx.x * 2 + r;

    // Cooperative load of W_hh rows [0, KS) into smem
    {
        const float4* Wg4 = (const float4*)W_hh;
        float4* Wsh4 = (float4*)Wsh;
#pragma unroll 4
        for (int i = tid; i < KS * H_DIM / 4; i += 256) Wsh4[i] = Wg4[i];
    }

    // Tail weights (k in [KS, 256)) resident in registers: wr[2k], wr[2k+1]
    float wr[64];
#pragma unroll
    for (int k = 0; k < 32; k++) {
        float2 w = *(const float2*)&W_hh[(size_t)(KS + k) * H_DIM + h0];
        wr[2 * k + 0] = w.x;
        wr[2 * k + 1] = w.y;
    }

    // Zero initial state
    S[tid] = 0.0f;
    S[256 + tid] = 0.0f;
    __syncthreads();

    float* sr = S + r * H_DIM;
    float* state_out = out + (size_t)T_DIM * B_DIM * H_DIM;

    // Prefetch X[0]
    float2 xpre = *(const float2*)&g_X[((size_t)b) * H_DIM + h0];

    for (int t = 0; t < T_DIM; t++) {
        const int tn = (t + 1 < T_DIM) ? (t + 1) : t;
        float2 xv = xpre;
        xpre = *(const float2*)&g_X[((size_t)tn * B_DIM + b) * H_DIM + h0];

        float a0 = xv.x, a1 = xv.y;

        // smem-resident part of W_hh
#pragma unroll 8
        for (int k = 0; k < KS; k += 4) {
            float4 s4 = *(const float4*)&sr[k];
            float2 w;
            w = *(const float2*)&Wsh[(k + 0) * H_DIM + h0];
            a0 = fmaf(s4.x, w.x, a0); a1 = fmaf(s4.x, w.y, a1);
            w = *(const float2*)&Wsh[(k + 1) * H_DIM + h0];
            a0 = fmaf(s4.y, w.x, a0); a1 = fmaf(s4.y, w.y, a1);
            w = *(const float2*)&Wsh[(k + 2) * H_DIM + h0];
            a0 = fmaf(s4.z, w.x, a0); a1 = fmaf(s4.z, w.y, a1);
            w = *(const float2*)&Wsh[(k + 3) * H_DIM + h0];
            a0 = fmaf(s4.w, w.x, a0); a1 = fmaf(s4.w, w.y, a1);
        }
        // register-resident tail of W_hh
#pragma unroll
        for (int j = 0; j < 32; j += 4) {
            float4 s4 = *(const float4*)&sr[KS + j];
            a0 = fmaf(s4.x, wr[2 * j + 0], a0); a1 = fmaf(s4.x, wr[2 * j + 1], a1);
            a0 = fmaf(s4.y, wr[2 * j + 2], a0); a1 = fmaf(s4.y, wr[2 * j + 3], a1);
            a0 = fmaf(s4.z, wr[2 * j + 4], a0); a1 = fmaf(s4.z, wr[2 * j + 5], a1);
            a0 = fmaf(s4.w, wr[2 * j + 6], a0); a1 = fmaf(s4.w, wr[2 * j + 7], a1);
        }

        float v0 = tanhf(a0);
        float v1 = tanhf(a1);

        __syncthreads();                 // all reads of old state done
        sr[h0] = v0;
        sr[h0 + 1] = v1;

        float2 vv = make_float2(v0, v1);
        *(float2*)&out[((size_t)t * B_DIM + b) * H_DIM + h0] = vv;
        if (write_state && t == T_DIM - 1)
            *(float2*)&state_out[(size_t)b * H_DIM + h0] = vv;

        __syncthreads();                 // new state visible before next step
    }
}

// ---------------------------------------------------------------------------
// Launch
// ---------------------------------------------------------------------------
extern "C" void kernel_launch(void* const* d_in, const int* in_sizes, int n_in,
                              void* d_out, int out_size)
{
    (void)n_in; (void)in_sizes;
    const float* inputs = (const float*)d_in[0];  // [T,B,I]
    const float* W_xh   = (const float*)d_in[1];  // [I,H]
    const float* W_hh   = (const float*)d_in[2];  // [H,H]
    const float* b_h    = (const float*)d_in[3];  // [H]
    float* out = (float*)d_out;

    // Does d_out include the trailing final-state tensor?
    const long long need = (long long)T_DIM * B_DIM * H_DIM + (long long)B_DIM * H_DIM;
    int write_state = ((long long)out_size >= need) ? 1 : 0;

    // Kernel 1: input projection into g_X
    dim3 g1(M_DIM / BM, H_DIM / BN);
    gemm_xh_kernel<<<g1, 256>>>(inputs, W_xh, b_h);

    // Kernel 2: recurrence (stream-ordered after kernel 1)
    cudaFuncSetAttribute(rnn_kernel, cudaFuncAttributeMaxDynamicSharedMemorySize,
                         RNN_SMEM_BYTES);
    rnn_kernel<<<B_DIM / 2, 256, RNN_SMEM_BYTES>>>(W_hh, out, write_state);
}

// round 3
// speedup vs baseline: 1.3539x; 1.3539x over previous
#include <cuda_runtime.h>

// Problem constants (fixed by the reference)
#define T_DIM 1024
#define B_DIM 256
#define I_DIM 256
#define H_DIM 256
#define M_DIM (T_DIM * B_DIM)

// Scratch for X = inputs @ W_xh + b_h  (fp32, 268 MB)
__device__ float g_X[(size_t)M_DIM * H_DIM];

// ---------------------------------------------------------------------------
// packed f32x2 helpers
// ---------------------------------------------------------------------------
__device__ __forceinline__ void ffma2(unsigned long long& d,
                                      unsigned long long a,
                                      unsigned long long b) {
    asm("fma.rn.f32x2 %0, %1, %2, %0;" : "+l"(d) : "l"(a), "l"(b));
}
__device__ __forceinline__ unsigned long long fadd2(unsigned long long a,
                                                    unsigned long long b) {
    unsigned long long d;
    asm("add.rn.f32x2 %0, %1, %2;" : "=l"(d) : "l"(a), "l"(b));
    return d;
}
__device__ __forceinline__ unsigned long long pk2(float lo, float hi) {
    unsigned long long d;
    asm("mov.b64 %0, {%1, %2};" : "=l"(d) : "f"(lo), "f"(hi));
    return d;
}
__device__ __forceinline__ float2 upk2(unsigned long long a) {
    float2 v;
    asm("mov.b64 {%0, %1}, %2;" : "=f"(v.x), "=f"(v.y) : "l"(a));
    return v;
}

// ---------------------------------------------------------------------------
// Kernel 1: X = inputs @ W_xh + b_h   (unchanged, known-good 128x128x8 SGEMM)
// ---------------------------------------------------------------------------
#define BM 128
#define BN 128
#define BK 8
#define TM 8
#define TN 8

__global__ __launch_bounds__(256) void gemm_xh_kernel(
    const float* __restrict__ A,
    const float* __restrict__ Bw,
    const float* __restrict__ bias)
{
    __shared__ float As[BK * BM];
    __shared__ float Bs[BK * BN];

    const int mTile = blockIdx.x;
    const int nTile = blockIdx.y;
    const int tid = threadIdx.x;

    const int tx = tid % (BN / TN);
    const int ty = tid / (BN / TN);

    const int aRow = tid >> 1;
    const int aCol = (tid & 1) * 4;
    const int bRow = tid >> 5;
    const int bCol = (tid & 31) * 4;

    const float* Ag = A + (size_t)mTile * BM * I_DIM;
    const float* Bg = Bw + nTile * BN;

    float acc[TM][TN];
#pragma unroll
    for (int i = 0; i < TM; i++)
#pragma unroll
        for (int j = 0; j < TN; j++) acc[i][j] = 0.0f;

    for (int k0 = 0; k0 < I_DIM; k0 += BK) {
        float4 a = *(const float4*)&Ag[(size_t)aRow * I_DIM + k0 + aCol];
        As[(aCol + 0) * BM + aRow] = a.x;
        As[(aCol + 1) * BM + aRow] = a.y;
        As[(aCol + 2) * BM + aRow] = a.z;
        As[(aCol + 3) * BM + aRow] = a.w;
        float4 b = *(const float4*)&Bg[(size_t)(k0 + bRow) * H_DIM + bCol];
        *(float4*)&Bs[bRow * BN + bCol] = b;
        __syncthreads();

#pragma unroll
        for (int k = 0; k < BK; k++) {
            float rM[TM], rN[TN];
            float4 m0 = *(const float4*)&As[k * BM + ty * TM + 0];
            float4 m1 = *(const float4*)&As[k * BM + ty * TM + 4];
            rM[0] = m0.x; rM[1] = m0.y; rM[2] = m0.z; rM[3] = m0.w;
            rM[4] = m1.x; rM[5] = m1.y; rM[6] = m1.z; rM[7] = m1.w;
            float4 n0 = *(const float4*)&Bs[k * BN + tx * TN + 0];
            float4 n1 = *(const float4*)&Bs[k * BN + tx * TN + 4];
            rN[0] = n0.x; rN[1] = n0.y; rN[2] = n0.z; rN[3] = n0.w;
            rN[4] = n1.x; rN[5] = n1.y; rN[6] = n1.z; rN[7] = n1.w;
#pragma unroll
            for (int i = 0; i < TM; i++)
#pragma unroll
                for (int j = 0; j < TN; j++)
                    acc[i][j] = fmaf(rM[i], rN[j], acc[i][j]);
        }
        __syncthreads();
    }

    const int nBase = nTile * BN + tx * TN;
    float bv[TN];
#pragma unroll
    for (int j = 0; j < TN; j++) bv[j] = bias[nBase + j];

#pragma unroll
    for (int i = 0; i < TM; i++) {
        size_t row = (size_t)mTile * BM + ty * TM + i;
        float4 o0, o1;
        o0.x = acc[i][0] + bv[0]; o0.y = acc[i][1] + bv[1];
        o0.z = acc[i][2] + bv[2]; o0.w = acc[i][3] + bv[3];
        o1.x = acc[i][4] + bv[4]; o1.y = acc[i][5] + bv[5];
        o1.z = acc[i][6] + bv[6]; o1.w = acc[i][7] + bv[7];
        *(float4*)&g_X[row * H_DIM + nBase + 0] = o0;
        *(float4*)&g_X[row * H_DIM + nBase + 4] = o1;
    }
}

// ---------------------------------------------------------------------------
// Kernel 2: the recurrence.
// 128 CTAs x 512 threads. CTA c owns batch rows 2c, 2c+1.
// Thread = (column-pair p in 0..127, k-split s in 0..3 of 64 k each).
//   lane = s*8 + (p % 8); warp = p / 8.
// Weights: k in [64s, 64s+32) live in registers (packed even/odd-k f32x2),
//          k in [64s+32, 64s+64) live in smem pre-packed for f32x2.
// Accumulators are f32x2 (lo = even-k partial, hi = odd-k partial).
// Split partials reduced via shfl.bfly(8), shfl.bfly(16); split-0 lanes
// add x + tanh + write state/out.
// ---------------------------------------------------------------------------
#define PAIR_STRIDE_F 68                      // 16 float4 + 1 pad float4 (272B)
#define SPLIT_STRIDE_F (128 * PAIR_STRIDE_F + 4)   // 8708 floats
#define SMEM_STATE_F 512
#define RNN_SMEM_F (SMEM_STATE_F + 4 * SPLIT_STRIDE_F)   // 35344 floats
#define RNN_SMEM_B (RNN_SMEM_F * 4)                      // 141376 bytes

__global__ __launch_bounds__(512, 1) void rnn_kernel(
    const float* __restrict__ W,      // W_hh [k][h]
    float* __restrict__ out,          // outputs [T,B,H] (+ optional state [B,H])
    int write_state)
{
    extern __shared__ float sm[];
    float* S = sm;                          // [2][256] state
    float* WP = sm + SMEM_STATE_F;          // packed weights

    const int tid = threadIdx.x;
    const int wid = tid >> 5;
    const int lane = tid & 31;
    const int p = wid * 8 + (lane & 7);     // column pair 0..127
    const int s = lane >> 3;                // k-split 0..3
    const int h0 = 2 * p;
    const int kbase = 64 * s;
    const int b0 = blockIdx.x * 2;
    const bool epi = (s == 0);

    // --- register-resident weights: k in [kbase, kbase+32), packed (k, k+1)
    unsigned long long wrA[16], wrB[16];    // columns h0 and h0+1
#pragma unroll
    for (int j = 0; j < 16; j++) {
        int k = kbase + 2 * j;
        float2 wk  = *(const float2*)&W[(size_t)k * H_DIM + h0];
        float2 wk1 = *(const float2*)&W[(size_t)(k + 1) * H_DIM + h0];
        wrA[j] = pk2(wk.x, wk1.x);
        wrB[j] = pk2(wk.y, wk1.y);
    }

    // --- smem-resident packed weights: k in [kbase+32, kbase+64)
    float* myWP = WP + s * SPLIT_STRIDE_F + p * PAIR_STRIDE_F;
#pragma unroll
    for (int j = 0; j < 16; j++) {
        int k = kbase + 32 + 2 * j;
        float2 wk  = *(const float2*)&W[(size_t)k * H_DIM + h0];
        float2 wk1 = *(const float2*)&W[(size_t)(k + 1) * H_DIM + h0];
        *(float4*)&myWP[4 * j] = make_float4(wk.x, wk1.x, wk.y, wk1.y);
    }

    // zero initial state
    S[tid & 511] = 0.0f;
    __syncthreads();

    const ulonglong2* wp2 = (const ulonglong2*)myWP;             // 16 entries
    const ulonglong2* su0 = (const ulonglong2*)&S[kbase];        // row 0, this split
    const ulonglong2* su1 = (const ulonglong2*)&S[H_DIM + kbase];// row 1
    float* state_out = out + (size_t)T_DIM * B_DIM * H_DIM;

    // prefetch X[0] for both rows (epi lanes only)
    float2 x0 = make_float2(0.f, 0.f), x1 = x0;
    if (epi) {
        x0 = *(const float2*)&g_X[((size_t)b0) * H_DIM + h0];
        x1 = *(const float2*)&g_X[((size_t)(b0 + 1)) * H_DIM + h0];
    }

    for (int t = 0; t < T_DIM; t++) {
        unsigned long long a00 = 0ull, a01 = 0ull, a10 = 0ull, a11 = 0ull;

        // register-weight half: k offsets [0,32)
#pragma unroll
        for (int j2 = 0; j2 < 8; j2++) {
            ulonglong2 s0 = su0[j2];
            ulonglong2 s1 = su1[j2];
            ffma2(a00, s0.x, wrA[2 * j2]);     ffma2(a01, s0.x, wrB[2 * j2]);
            ffma2(a00, s0.y, wrA[2 * j2 + 1]); ffma2(a01, s0.y, wrB[2 * j2 + 1]);
            ffma2(a10, s1.x, wrA[2 * j2]);     ffma2(a11, s1.x, wrB[2 * j2]);
            ffma2(a10, s1.y, wrA[2 * j2 + 1]); ffma2(a11, s1.y, wrB[2 * j2 + 1]);
        }
        // smem-weight half: k offsets [32,64)
#pragma unroll
        for (int j2 = 0; j2 < 8; j2++) {
            ulonglong2 w0 = wp2[2 * j2];
            ulonglong2 w1 = wp2[2 * j2 + 1];
            ulonglong2 s0 = su0[8 + j2];
            ulonglong2 s1 = su1[8 + j2];
            ffma2(a00, s0.x, w0.x); ffma2(a01, s0.x, w0.y);
            ffma2(a00, s0.y, w1.x); ffma2(a01, s0.y, w1.y);
            ffma2(a10, s1.x, w0.x); ffma2(a11, s1.x, w0.y);
            ffma2(a10, s1.y, w1.x); ffma2(a11, s1.y, w1.y);
        }

        // reduce over the 4 k-splits (lane bits 3,4)
        a00 = fadd2(a00, __shfl_xor_sync(0xffffffffu, a00, 8));
        a01 = fadd2(a01, __shfl_xor_sync(0xffffffffu, a01, 8));
        a10 = fadd2(a10, __shfl_xor_sync(0xffffffffu, a10, 8));
        a11 = fadd2(a11, __shfl_xor_sync(0xffffffffu, a11, 8));
        a00 = fadd2(a00, __shfl_xor_sync(0xffffffffu, a00, 16));
        a01 = fadd2(a01, __shfl_xor_sync(0xffffffffu, a01, 16));
        a10 = fadd2(a10, __shfl_xor_sync(0xffffffffu, a10, 16));
        a11 = fadd2(a11, __shfl_xor_sync(0xffffffffu, a11, 16));

        float h00, h01, h10, h11;
        if (epi) {
            float2 v;
            v = upk2(a00); h00 = tanhf(v.x + v.y + x0.x);
            v = upk2(a01); h01 = tanhf(v.x + v.y + x0.y);
            v = upk2(a10); h10 = tanhf(v.x + v.y + x1.x);
            v = upk2(a11); h11 = tanhf(v.x + v.y + x1.y);
            // prefetch next timestep's x while others head to the barrier
            int tn = (t + 1 < T_DIM) ? (t + 1) : t;
            x0 = *(const float2*)&g_X[((size_t)tn * B_DIM + b0) * H_DIM + h0];
            x1 = *(const float2*)&g_X[((size_t)tn * B_DIM + b0 + 1) * H_DIM + h0];
        }

        __syncthreads();   // all reads of the old state are complete
        if (epi) {
            *(float2*)&S[h0]         = make_float2(h00, h01);
            *(float2*)&S[H_DIM + h0] = make_float2(h10, h11);
            *(float2*)&out[((size_t)t * B_DIM + b0) * H_DIM + h0]     = make_float2(h00, h01);
            *(float2*)&out[((size_t)t * B_DIM + b0 + 1) * H_DIM + h0] = make_float2(h10, h11);
        }
        __syncthreads();   // new state visible before next step
    }

    if (write_state && epi) {
        *(float2*)&state_out[(size_t)b0 * H_DIM + h0]       = *(const float2*)&S[h0];
        *(float2*)&state_out[(size_t)(b0 + 1) * H_DIM + h0] = *(const float2*)&S[H_DIM + h0];
    }
}

// ---------------------------------------------------------------------------
// Launch
// ---------------------------------------------------------------------------
extern "C" void kernel_launch(void* const* d_in, const int* in_sizes, int n_in,
                              void* d_out, int out_size)
{
    (void)n_in; (void)in_sizes;
    const float* inputs = (const float*)d_in[0];  // [T,B,I]
    const float* W_xh   = (const float*)d_in[1];  // [I,H]
    const float* W_hh   = (const float*)d_in[2];  // [H,H]
    const float* b_h    = (const float*)d_in[3];  // [H]
    float* out = (float*)d_out;

    const long long need = (long long)T_DIM * B_DIM * H_DIM + (long long)B_DIM * H_DIM;
    int write_state = ((long long)out_size >= need) ? 1 : 0;

    dim3 g1(M_DIM / BM, H_DIM / BN);
    gemm_xh_kernel<<<g1, 256>>>(inputs, W_xh, b_h);

    cudaFuncSetAttribute(rnn_kernel, cudaFuncAttributeMaxDynamicSharedMemorySize,
                         RNN_SMEM_B);
    rnn_kernel<<<B_DIM / 2, 512, RNN_SMEM_B>>>(W_hh, out, write_state);
}

// round 4
// speedup vs baseline: 1.6574x; 1.2241x over previous
#include <cuda_runtime.h>

// Problem constants (fixed by the reference)
#define T_DIM 1024
#define B_DIM 256
#define I_DIM 256
#define H_DIM 256
#define M_DIM (T_DIM * B_DIM)

// Scratch for X = inputs @ W_xh + b_h  (fp32, 268 MB)
__device__ float g_X[(size_t)M_DIM * H_DIM];

// ---------------------------------------------------------------------------
// packed f32x2 helpers
// ---------------------------------------------------------------------------
__device__ __forceinline__ void ffma2(unsigned long long& d,
                                      unsigned long long a,
                                      unsigned long long b) {
    asm("fma.rn.f32x2 %0, %1, %2, %0;" : "+l"(d) : "l"(a), "l"(b));
}
__device__ __forceinline__ unsigned long long fadd2(unsigned long long a,
                                                    unsigned long long b) {
    unsigned long long d;
    asm("add.rn.f32x2 %0, %1, %2;" : "=l"(d) : "l"(a), "l"(b));
    return d;
}
__device__ __forceinline__ unsigned long long pk2(float lo, float hi) {
    unsigned long long d;
    asm("mov.b64 %0, {%1, %2};" : "=l"(d) : "f"(lo), "f"(hi));
    return d;
}
__device__ __forceinline__ float2 upk2(unsigned long long a) {
    float2 v;
    asm("mov.b64 {%0, %1}, %2;" : "=f"(v.x), "=f"(v.y) : "l"(a));
    return v;
}

// ---------------------------------------------------------------------------
// Kernel 1: X = inputs @ W_xh + b_h  (fp32 SGEMM, f32x2-packed accumulation)
// 128x128x8 tile, 256 threads. Each thread: 4 row-pairs x 8 cols, packed
// accumulators (lo = even row, hi = odd row). A row-pairs come pre-packed
// from the transposed As tile; rN is duplicated via alu-pipe movs.
// ---------------------------------------------------------------------------
#define BM 128
#define BN 128
#define BK 8
#define TM 8
#define TN 8

__global__ __launch_bounds__(256) void gemm_xh_kernel(
    const float* __restrict__ A,
    const float* __restrict__ Bw,
    const float* __restrict__ bias)
{
    __shared__ float As[BK * BM];   // transposed: As[k][m]
    __shared__ float Bs[BK * BN];   // Bs[k][n]

    const int mTile = blockIdx.x;
    const int nTile = blockIdx.y;
    const int tid = threadIdx.x;

    const int tx = tid % (BN / TN);   // 0..15
    const int ty = tid / (BN / TN);   // 0..15

    const int aRow = tid >> 1;
    const int aCol = (tid & 1) * 4;
    const int bRow = tid >> 5;
    const int bCol = (tid & 31) * 4;

    const float* Ag = A + (size_t)mTile * BM * I_DIM;
    const float* Bg = Bw + nTile * BN;

    unsigned long long acc2[4][TN];   // [row-pair][col]: lo=row 2i, hi=row 2i+1
#pragma unroll
    for (int i = 0; i < 4; i++)
#pragma unroll
        for (int j = 0; j < TN; j++) acc2[i][j] = 0ull;

    for (int k0 = 0; k0 < I_DIM; k0 += BK) {
        float4 a = *(const float4*)&Ag[(size_t)aRow * I_DIM + k0 + aCol];
        As[(aCol + 0) * BM + aRow] = a.x;
        As[(aCol + 1) * BM + aRow] = a.y;
        As[(aCol + 2) * BM + aRow] = a.z;
        As[(aCol + 3) * BM + aRow] = a.w;
        float4 b = *(const float4*)&Bg[(size_t)(k0 + bRow) * H_DIM + bCol];
        *(float4*)&Bs[bRow * BN + bCol] = b;
        __syncthreads();

#pragma unroll
        for (int k = 0; k < BK; k++) {
            // row-pairs, naturally packed (m contiguous in transposed As)
            ulonglong2 am0 = *(const ulonglong2*)&As[k * BM + ty * TM + 0];
            ulonglong2 am1 = *(const ulonglong2*)&As[k * BM + ty * TM + 4];
            unsigned long long ap[4] = {am0.x, am0.y, am1.x, am1.y};
            float4 n0 = *(const float4*)&Bs[k * BN + tx * TN + 0];
            float4 n1 = *(const float4*)&Bs[k * BN + tx * TN + 4];
            unsigned long long bd[TN];
            bd[0] = pk2(n0.x, n0.x); bd[1] = pk2(n0.y, n0.y);
            bd[2] = pk2(n0.z, n0.z); bd[3] = pk2(n0.w, n0.w);
            bd[4] = pk2(n1.x, n1.x); bd[5] = pk2(n1.y, n1.y);
            bd[6] = pk2(n1.z, n1.z); bd[7] = pk2(n1.w, n1.w);
#pragma unroll
            for (int i = 0; i < 4; i++)
#pragma unroll
                for (int j = 0; j < TN; j++)
                    ffma2(acc2[i][j], ap[i], bd[j]);
        }
        __syncthreads();
    }

    // Epilogue: unpack, add bias, store
    const int nBase = nTile * BN + tx * TN;
    float bv[TN];
#pragma unroll
    for (int j = 0; j < TN; j++) bv[j] = bias[nBase + j];

#pragma unroll
    for (int i = 0; i < 4; i++) {
        size_t row0 = (size_t)mTile * BM + ty * TM + 2 * i;
        float r0[TN], r1[TN];
#pragma unroll
        for (int j = 0; j < TN; j++) {
            float2 v = upk2(acc2[i][j]);
            r0[j] = v.x + bv[j];
            r1[j] = v.y + bv[j];
        }
        *(float4*)&g_X[row0 * H_DIM + nBase + 0] = make_float4(r0[0], r0[1], r0[2], r0[3]);
        *(float4*)&g_X[row0 * H_DIM + nBase + 4] = make_float4(r0[4], r0[5], r0[6], r0[7]);
        *(float4*)&g_X[(row0 + 1) * H_DIM + nBase + 0] = make_float4(r1[0], r1[1], r1[2], r1[3]);
        *(float4*)&g_X[(row0 + 1) * H_DIM + nBase + 4] = make_float4(r1[4], r1[5], r1[6], r1[7]);
    }
}

// ---------------------------------------------------------------------------
// Kernel 2: the recurrence.
// 128 CTAs x 512 threads; CTA owns batch rows 2c, 2c+1.
// Thread = (column-pair p 0..127, k-split s 0..3). lane = s*8 + (p%8).
// State layout is SKEWED: row stride 272 floats, +4-float pad per 64-float
// chunk, so the 4 splits' reads land on distinct bank quads (byte offset
// 272s mod 128 = {0,16,32,48}) -> conflict-free broadcast LDS.128.
// ---------------------------------------------------------------------------
#define SROW 272                               // skewed state row stride (floats)
#define PAIR_STRIDE_F 68                       // 16 data float4 + 1 pad float4
#define SPLIT_STRIDE_F (128 * PAIR_STRIDE_F + 4)
#define SMEM_STATE_F (2 * SROW)                // 544
#define RNN_SMEM_F (SMEM_STATE_F + 4 * SPLIT_STRIDE_F)
#define RNN_SMEM_B (RNN_SMEM_F * 4)

__global__ __launch_bounds__(512, 1) void rnn_kernel(
    const float* __restrict__ W,      // W_hh [k][h]
    float* __restrict__ out,          // outputs [T,B,H] (+ optional state [B,H])
    int write_state)
{
    extern __shared__ float sm[];
    float* Ss = sm;                         // skewed state [2][SROW]
    float* WP = sm + SMEM_STATE_F;          // packed weights

    const int tid = threadIdx.x;
    const int wid = tid >> 5;
    const int lane = tid & 31;
    const int p = wid * 8 + (lane & 7);     // column pair 0..127
    const int s = lane >> 3;                // k-split 0..3
    const int h0 = 2 * p;
    const int kbase = 64 * s;
    const int b0 = blockIdx.x * 2;
    const bool epi = (s == 0);
    const int hs = h0 + ((h0 >> 6) << 2);   // skewed state index for h0

    // register-resident weights: k in [kbase, kbase+32), packed (k, k+1)
    unsigned long long wrA[16], wrB[16];
#pragma unroll
    for (int j = 0; j < 16; j++) {
        int k = kbase + 2 * j;
        float2 wk  = *(const float2*)&W[(size_t)k * H_DIM + h0];
        float2 wk1 = *(const float2*)&W[(size_t)(k + 1) * H_DIM + h0];
        wrA[j] = pk2(wk.x, wk1.x);
        wrB[j] = pk2(wk.y, wk1.y);
    }

    // smem-resident packed weights: k in [kbase+32, kbase+64)
    float* myWP = WP + s * SPLIT_STRIDE_F + p * PAIR_STRIDE_F;
#pragma unroll
    for (int j = 0; j < 16; j++) {
        int k = kbase + 32 + 2 * j;
        float2 wk  = *(const float2*)&W[(size_t)k * H_DIM + h0];
        float2 wk1 = *(const float2*)&W[(size_t)(k + 1) * H_DIM + h0];
        *(float4*)&myWP[4 * j] = make_float4(wk.x, wk1.x, wk.y, wk1.y);
    }

    // zero initial state (incl. pads)
    for (int i = tid; i < SMEM_STATE_F; i += 512) Ss[i] = 0.0f;
    __syncthreads();

    const ulonglong2* wp2 = (const ulonglong2*)myWP;
    const ulonglong2* su0 = (const ulonglong2*)&Ss[68 * s];          // row 0
    const ulonglong2* su1 = (const ulonglong2*)&Ss[SROW + 68 * s];   // row 1
    float* state_out = out + (size_t)T_DIM * B_DIM * H_DIM;

    float2 x0 = make_float2(0.f, 0.f), x1 = x0;
    if (epi) {
        x0 = *(const float2*)&g_X[((size_t)b0) * H_DIM + h0];
        x1 = *(const float2*)&g_X[((size_t)(b0 + 1)) * H_DIM + h0];
    }

    for (int t = 0; t < T_DIM; t++) {
        unsigned long long a00 = 0ull, a01 = 0ull, a10 = 0ull, a11 = 0ull;

        // register-weight half: k offsets [0,32)
#pragma unroll
        for (int j2 = 0; j2 < 8; j2++) {
            ulonglong2 s0 = su0[j2];
            ulonglong2 s1 = su1[j2];
            ffma2(a00, s0.x, wrA[2 * j2]);     ffma2(a01, s0.x, wrB[2 * j2]);
            ffma2(a00, s0.y, wrA[2 * j2 + 1]); ffma2(a01, s0.y, wrB[2 * j2 + 1]);
            ffma2(a10, s1.x, wrA[2 * j2]);     ffma2(a11, s1.x, wrB[2 * j2]);
            ffma2(a10, s1.y, wrA[2 * j2 + 1]); ffma2(a11, s1.y, wrB[2 * j2 + 1]);
        }
        // smem-weight half: k offsets [32,64)
#pragma unroll
        for (int j2 = 0; j2 < 8; j2++) {
            ulonglong2 w0 = wp2[2 * j2];
            ulonglong2 w1 = wp2[2 * j2 + 1];
            ulonglong2 s0 = su0[8 + j2];
            ulonglong2 s1 = su1[8 + j2];
            ffma2(a00, s0.x, w0.x); ffma2(a01, s0.x, w0.y);
            ffma2(a00, s0.y, w1.x); ffma2(a01, s0.y, w1.y);
            ffma2(a10, s1.x, w0.x); ffma2(a11, s1.x, w0.y);
            ffma2(a10, s1.y, w1.x); ffma2(a11, s1.y, w1.y);
        }

        // reduce over the 4 k-splits (lane bits 3,4)
        a00 = fadd2(a00, __shfl_xor_sync(0xffffffffu, a00, 8));
        a01 = fadd2(a01, __shfl_xor_sync(0xffffffffu, a01, 8));
        a10 = fadd2(a10, __shfl_xor_sync(0xffffffffu, a10, 8));
        a11 = fadd2(a11, __shfl_xor_sync(0xffffffffu, a11, 8));
        a00 = fadd2(a00, __shfl_xor_sync(0xffffffffu, a00, 16));
        a01 = fadd2(a01, __shfl_xor_sync(0xffffffffu, a01, 16));
        a10 = fadd2(a10, __shfl_xor_sync(0xffffffffu, a10, 16));
        a11 = fadd2(a11, __shfl_xor_sync(0xffffffffu, a11, 16));

        float h00, h01, h10, h11;
        if (epi) {
            float2 v;
            v = upk2(a00); h00 = tanhf(v.x + v.y + x0.x);
            v = upk2(a01); h01 = tanhf(v.x + v.y + x0.y);
            v = upk2(a10); h10 = tanhf(v.x + v.y + x1.x);
            v = upk2(a11); h11 = tanhf(v.x + v.y + x1.y);
            int tn = (t + 1 < T_DIM) ? (t + 1) : t;
            x0 = *(const float2*)&g_X[((size_t)tn * B_DIM + b0) * H_DIM + h0];
            x1 = *(const float2*)&g_X[((size_t)tn * B_DIM + b0 + 1) * H_DIM + h0];
        }

        __syncthreads();   // all reads of the old state complete
        if (epi) {
            *(float2*)&Ss[hs]        = make_float2(h00, h01);
            *(float2*)&Ss[SROW + hs] = make_float2(h10, h11);
            *(float2*)&out[((size_t)t * B_DIM + b0) * H_DIM + h0]     = make_float2(h00, h01);
            *(float2*)&out[((size_t)t * B_DIM + b0 + 1) * H_DIM + h0] = make_float2(h10, h11);
        }
        __syncthreads();   // new state visible before next step
    }

    if (write_state && epi) {
        *(float2*)&state_out[(size_t)b0 * H_DIM + h0]       = *(const float2*)&Ss[hs];
        *(float2*)&state_out[(size_t)(b0 + 1) * H_DIM + h0] = *(const float2*)&Ss[SROW + hs];
    }
}

// ---------------------------------------------------------------------------
// Launch
// ---------------------------------------------------------------------------
extern "C" void kernel_launch(void* const* d_in, const int* in_sizes, int n_in,
                              void* d_out, int out_size)
{
    (void)n_in; (void)in_sizes;
    const float* inputs = (const float*)d_in[0];  // [T,B,I]
    const float* W_xh   = (const float*)d_in[1];  // [I,H]
    const float* W_hh   = (const float*)d_in[2];  // [H,H]
    const float* b_h    = (const float*)d_in[3];  // [H]
    float* out = (float*)d_out;

    const long long need = (long long)T_DIM * B_DIM * H_DIM + (long long)B_DIM * H_DIM;
    int write_state = ((long long)out_size >= need) ? 1 : 0;

    dim3 g1(M_DIM / BM, H_DIM / BN);
    gemm_xh_kernel<<<g1, 256>>>(inputs, W_xh, b_h);

    cudaFuncSetAttribute(rnn_kernel, cudaFuncAttributeMaxDynamicSharedMemorySize,
                         RNN_SMEM_B);
    rnn_kernel<<<B_DIM / 2, 512, RNN_SMEM_B>>>(W_hh, out, write_state);
}

// round 5
// speedup vs baseline: 1.8862x; 1.1381x over previous
#include <cuda_runtime.h>

// Problem constants (fixed by the reference)
#define T_DIM 1024
#define B_DIM 256
#define I_DIM 256
#define H_DIM 256
#define M_DIM (T_DIM * B_DIM)

// Scratch for X = inputs @ W_xh + b_h  (fp32, 268 MB)
__device__ float g_X[(size_t)M_DIM * H_DIM];

// ---------------------------------------------------------------------------
// packed f32x2 helpers
// ---------------------------------------------------------------------------
__device__ __forceinline__ void ffma2(unsigned long long& d,
                                      unsigned long long a,
                                      unsigned long long b) {
    asm("fma.rn.f32x2 %0, %1, %2, %0;" : "+l"(d) : "l"(a), "l"(b));
}
__device__ __forceinline__ unsigned long long pk2(float lo, float hi) {
    unsigned long long d;
    asm("mov.b64 %0, {%1, %2};" : "=l"(d) : "f"(lo), "f"(hi));
    return d;
}
__device__ __forceinline__ float2 upk2(unsigned long long a) {
    float2 v;
    asm("mov.b64 {%0, %1}, %2;" : "=f"(v.x), "=f"(v.y) : "l"(a));
    return v;
}
// sum of the two packed lanes
__device__ __forceinline__ float hsum2(unsigned long long a) {
    float2 v = upk2(a);
    return v.x + v.y;
}
// fast, accurate tanh: (e^{2x}-1) * rcp(e^{2x}+1); abs err ~1e-7 for |x|<~20
__device__ __forceinline__ float fast_tanh(float x) {
    float e, r;
    asm("ex2.approx.f32 %0, %1;" : "=f"(e) : "f"(x * 2.8853900817779268f));
    asm("rcp.approx.f32 %0, %1;" : "=f"(r) : "f"(e + 1.0f));
    return (e - 1.0f) * r;
}

// ---------------------------------------------------------------------------
// Kernel 1: X = inputs @ W_xh + b_h  (fp32 SGEMM, f32x2-packed accumulation)
// ---------------------------------------------------------------------------
#define BM 128
#define BN 128
#define BK 8
#define TM 8
#define TN 8

__global__ __launch_bounds__(256) void gemm_xh_kernel(
    const float* __restrict__ A,
    const float* __restrict__ Bw,
    const float* __restrict__ bias)
{
    __shared__ float As[BK * BM];
    __shared__ float Bs[BK * BN];

    const int mTile = blockIdx.x;
    const int nTile = blockIdx.y;
    const int tid = threadIdx.x;

    const int tx = tid % (BN / TN);
    const int ty = tid / (BN / TN);

    const int aRow = tid >> 1;
    const int aCol = (tid & 1) * 4;
    const int bRow = tid >> 5;
    const int bCol = (tid & 31) * 4;

    const float* Ag = A + (size_t)mTile * BM * I_DIM;
    const float* Bg = Bw + nTile * BN;

    unsigned long long acc2[4][TN];
#pragma unroll
    for (int i = 0; i < 4; i++)
#pragma unroll
        for (int j = 0; j < TN; j++) acc2[i][j] = 0ull;

    for (int k0 = 0; k0 < I_DIM; k0 += BK) {
        float4 a = *(const float4*)&Ag[(size_t)aRow * I_DIM + k0 + aCol];
        As[(aCol + 0) * BM + aRow] = a.x;
        As[(aCol + 1) * BM + aRow] = a.y;
        As[(aCol + 2) * BM + aRow] = a.z;
        As[(aCol + 3) * BM + aRow] = a.w;
        float4 b = *(const float4*)&Bg[(size_t)(k0 + bRow) * H_DIM + bCol];
        *(float4*)&Bs[bRow * BN + bCol] = b;
        __syncthreads();

#pragma unroll
        for (int k = 0; k < BK; k++) {
            ulonglong2 am0 = *(const ulonglong2*)&As[k * BM + ty * TM + 0];
            ulonglong2 am1 = *(const ulonglong2*)&As[k * BM + ty * TM + 4];
            unsigned long long ap[4] = {am0.x, am0.y, am1.x, am1.y};
            float4 n0 = *(const float4*)&Bs[k * BN + tx * TN + 0];
            float4 n1 = *(const float4*)&Bs[k * BN + tx * TN + 4];
            unsigned long long bd[TN];
            bd[0] = pk2(n0.x, n0.x); bd[1] = pk2(n0.y, n0.y);
            bd[2] = pk2(n0.z, n0.z); bd[3] = pk2(n0.w, n0.w);
            bd[4] = pk2(n1.x, n1.x); bd[5] = pk2(n1.y, n1.y);
            bd[6] = pk2(n1.z, n1.z); bd[7] = pk2(n1.w, n1.w);
#pragma unroll
            for (int i = 0; i < 4; i++)
#pragma unroll
                for (int j = 0; j < TN; j++)
                    ffma2(acc2[i][j], ap[i], bd[j]);
        }
        __syncthreads();
    }

    const int nBase = nTile * BN + tx * TN;
    float bv[TN];
#pragma unroll
    for (int j = 0; j < TN; j++) bv[j] = bias[nBase + j];

#pragma unroll
    for (int i = 0; i < 4; i++) {
        size_t row0 = (size_t)mTile * BM + ty * TM + 2 * i;
        float r0[TN], r1[TN];
#pragma unroll
        for (int j = 0; j < TN; j++) {
            float2 v = upk2(acc2[i][j]);
            r0[j] = v.x + bv[j];
            r1[j] = v.y + bv[j];
        }
        *(float4*)&g_X[row0 * H_DIM + nBase + 0] = make_float4(r0[0], r0[1], r0[2], r0[3]);
        *(float4*)&g_X[row0 * H_DIM + nBase + 4] = make_float4(r0[4], r0[5], r0[6], r0[7]);
        *(float4*)&g_X[(row0 + 1) * H_DIM + nBase + 0] = make_float4(r1[0], r1[1], r1[2], r1[3]);
        *(float4*)&g_X[(row0 + 1) * H_DIM + nBase + 4] = make_float4(r1[4], r1[5], r1[6], r1[7]);
    }
}

// ---------------------------------------------------------------------------
// Kernel 2: the recurrence.
// 128 CTAs x 512 threads; CTA owns batch rows 2c, 2c+1.
// Thread = (column-pair p 0..127, k-split s 0..3). lane = s*8 + (p%8).
// Double-buffered skewed state (one barrier per step). Balanced epilogue:
// 2-level scalar reduce-scatter (3 SHFLs), every thread finishes exactly one
// output element h[row = s>>1][2p + (s&1)] -> tanh -> STS + STG.
// ---------------------------------------------------------------------------
#define SROW 272                               // skewed state row stride (floats)
#define BUF_F (2 * SROW)                       // one state buffer (2 rows)
#define PAIR_STRIDE_F 68
#define SPLIT_STRIDE_F (128 * PAIR_STRIDE_F + 4)
#define SMEM_STATE_F (2 * BUF_F)               // two buffers
#define RNN_SMEM_F (SMEM_STATE_F + 4 * SPLIT_STRIDE_F)
#define RNN_SMEM_B (RNN_SMEM_F * 4)

__global__ __launch_bounds__(512, 1) void rnn_kernel(
    const float* __restrict__ W,      // W_hh [k][h]
    float* __restrict__ out,          // outputs [T,B,H] (+ optional state [B,H])
    int write_state)
{
    extern __shared__ float sm[];
    float* S0 = sm;                         // state buffer A
    float* S1 = sm + BUF_F;                 // state buffer B
    float* WP = sm + SMEM_STATE_F;          // packed weights

    const int tid = threadIdx.x;
    const int wid = tid >> 5;
    const int lane = tid & 31;
    const int p = wid * 8 + (lane & 7);     // column pair 0..127
    const int s = lane >> 3;                // k-split 0..3
    const int h0 = 2 * p;
    const int kbase = 64 * s;
    const int bidx0 = blockIdx.x * 2;
    const int hs = h0 + ((h0 >> 6) << 2);   // skewed state index for h0
    const bool sb0 = (s & 1);               // output column parity
    const int sb1 = (s >> 1);               // output row within the CTA pair

    // register-resident weights: k in [kbase, kbase+32), packed (k, k+1)
    unsigned long long wrA[16], wrB[16];
#pragma unroll
    for (int j = 0; j < 16; j++) {
        int k = kbase + 2 * j;
        float2 wk  = *(const float2*)&W[(size_t)k * H_DIM + h0];
        float2 wk1 = *(const float2*)&W[(size_t)(k + 1) * H_DIM + h0];
        wrA[j] = pk2(wk.x, wk1.x);
        wrB[j] = pk2(wk.y, wk1.y);
    }

    // smem-resident packed weights: k in [kbase+32, kbase+64)
    float* myWP = WP + s * SPLIT_STRIDE_F + p * PAIR_STRIDE_F;
#pragma unroll
    for (int j = 0; j < 16; j++) {
        int k = kbase + 32 + 2 * j;
        float2 wk  = *(const float2*)&W[(size_t)k * H_DIM + h0];
        float2 wk1 = *(const float2*)&W[(size_t)(k + 1) * H_DIM + h0];
        *(float4*)&myWP[4 * j] = make_float4(wk.x, wk1.x, wk.y, wk1.y);
    }

    // zero both state buffers (incl. pads)
    for (int i = tid; i < SMEM_STATE_F; i += 512) sm[i] = 0.0f;
    __syncthreads();

    const ulonglong2* wp2 = (const ulonglong2*)myWP;
    // per-thread addresses
    const int stoff = sb1 * SROW + hs + (sb0 ? 1 : 0);       // smem state store
    const size_t goff = (size_t)(bidx0 + sb1) * H_DIM + h0 + (sb0 ? 1 : 0);
    float* outp = out + goff;                                 // advances 65536/step
    const float* xp = g_X + goff;
    float* state_out = out + (size_t)T_DIM * B_DIM * H_DIM + goff;

    float x_nxt = *xp;   // x(t=0)

    // one timestep: read state from Sr, write new state to Sw
    auto step = [&](int t, const float* Sr, float* Sw) {
        const ulonglong2* su0 = (const ulonglong2*)(Sr + 68 * s);
        const ulonglong2* su1 = (const ulonglong2*)(Sr + SROW + 68 * s);

        float x_cur = x_nxt;
        // prefetch next step's x (one element/thread; latency hidden by matvec)
        int tn = (t + 1 < T_DIM) ? (t + 1) : t;
        x_nxt = xp[(size_t)(tn) * (B_DIM * H_DIM)];

        unsigned long long a00 = 0ull, a01 = 0ull, a10 = 0ull, a11 = 0ull;

        // register-weight half: k offsets [0,32)
#pragma unroll
        for (int j2 = 0; j2 < 8; j2++) {
            ulonglong2 s0 = su0[j2];
            ulonglong2 s1 = su1[j2];
            ffma2(a00, s0.x, wrA[2 * j2]);     ffma2(a01, s0.x, wrB[2 * j2]);
            ffma2(a00, s0.y, wrA[2 * j2 + 1]); ffma2(a01, s0.y, wrB[2 * j2 + 1]);
            ffma2(a10, s1.x, wrA[2 * j2]);     ffma2(a11, s1.x, wrB[2 * j2]);
            ffma2(a10, s1.y, wrA[2 * j2 + 1]); ffma2(a11, s1.y, wrB[2 * j2 + 1]);
        }
        // smem-weight half: k offsets [32,64)
#pragma unroll
        for (int j2 = 0; j2 < 8; j2++) {
            ulonglong2 w0 = wp2[2 * j2];
            ulonglong2 w1 = wp2[2 * j2 + 1];
            ulonglong2 s0 = su0[8 + j2];
            ulonglong2 s1 = su1[8 + j2];
            ffma2(a00, s0.x, w0.x); ffma2(a01, s0.x, w0.y);
            ffma2(a00, s0.y, w1.x); ffma2(a01, s0.y, w1.y);
            ffma2(a10, s1.x, w0.x); ffma2(a11, s1.x, w0.y);
            ffma2(a10, s1.y, w1.x); ffma2(a11, s1.y, w1.y);
        }

        // collapse packed lanes to scalars
        float f00 = hsum2(a00), f01 = hsum2(a01);
        float f10 = hsum2(a10), f11 = hsum2(a11);

        // 2-level reduce-scatter over the 4 k-splits (3 scalar SHFLs)
        float m0 = sb0 ? f01 : f00;
        float m1 = sb0 ? f11 : f10;
        float o0 = sb0 ? f00 : f01;
        float o1 = sb0 ? f10 : f11;
        m0 += __shfl_xor_sync(0xffffffffu, o0, 8);
        m1 += __shfl_xor_sync(0xffffffffu, o1, 8);
        float mm = sb1 ? m1 : m0;
        float oo = sb1 ? m0 : m1;
        mm += __shfl_xor_sync(0xffffffffu, oo, 16);

        float h = fast_tanh(mm + x_cur);

        Sw[stoff] = h;
        outp[(size_t)t * (B_DIM * H_DIM)] = h;
        if (write_state && t == T_DIM - 1) *state_out = h;

        __syncthreads();   // new state visible; old buffer free for overwrite
    };

#pragma unroll 1
    for (int t = 0; t < T_DIM; t += 2) {
        step(t,     S0, S1);
        step(t + 1, S1, S0);
    }
}

// ---------------------------------------------------------------------------
// Launch
// ---------------------------------------------------------------------------
extern "C" void kernel_launch(void* const* d_in, const int* in_sizes, int n_in,
                              void* d_out, int out_size)
{
    (void)n_in; (void)in_sizes;
    const float* inputs = (const float*)d_in[0];  // [T,B,I]
    const float* W_xh   = (const float*)d_in[1];  // [I,H]
    const float* W_hh   = (const float*)d_in[2];  // [H,H]
    const float* b_h    = (const float*)d_in[3];  // [H]
    float* out = (float*)d_out;

    const long long need = (long long)T_DIM * B_DIM * H_DIM + (long long)B_DIM * H_DIM;
    int write_state = ((long long)out_size >= need) ? 1 : 0;

    dim3 g1(M_DIM / BM, H_DIM / BN);
    gemm_xh_kernel<<<g1, 256>>>(inputs, W_xh, b_h);

    cudaFuncSetAttribute(rnn_kernel, cudaFuncAttributeMaxDynamicSharedMemorySize,
                         RNN_SMEM_B);
    rnn_kernel<<<B_DIM / 2, 512, RNN_SMEM_B>>>(W_hh, out, write_state);
}